// round 2
// baseline (speedup 1.0000x reference)
#include <cuda_runtime.h>
#include <math.h>

// ---------------------------------------------------------------------------
// SPINN shift-reduce TreeLSTM, fp32 SIMT baseline.
//
// Shapes: B=128, L=128, E=512, H=512, T=255, S=L+2=130
// Inputs (metadata order):
//   0 sentence    float [128,128,512]
//   1 transitions int32 [128,255]
//   2 word_W      float [512,1024]
//   3 word_b      float [1024]
//   4 bn_gamma    float [1024]
//   5 bn_beta     float [1024]
//   6 reduce_W    float [1024,2560]
//   7 reduce_b    float [2560]
// Output: float [128,512]
// ---------------------------------------------------------------------------

#define BB 128
#define LL 128
#define EE 512
#define HH 512
#define TT 255
#define SS 130
#define NLE (BB*LL)        // 16384
#define TWO_H 1024
#define FIVE_H 2560

// ------------------------- scratch (static device memory) ------------------
__device__ float g_tmp[NLE * TWO_H];            // word gemm output (pre-BN)   67 MB
__device__ float g_hbuf[BB * LL * HH];          // BN'd h word buffer          33.5 MB
__device__ float g_cbuf[BB * LL * HH];          // BN'd c word buffer          33.5 MB
__device__ float g_stack_h[BB * SS * HH];       // stack h                     34 MB
__device__ float g_stack_c[BB * SS * HH];       // stack c                     34 MB
__device__ float g_x[2][BB * TWO_H];            // double-buffered gather x
__device__ float g_sum[TWO_H];
__device__ float g_sumsq[TWO_H];
__device__ float g_scale[TWO_H];
__device__ float g_shift[TWO_H];
__device__ int   g_i1[TT * BB];
__device__ int   g_i2[TT * BB];
__device__ int   g_pos[TT * BB];
__device__ int   g_bi[TT * BB];
__device__ int   g_flg[TT * BB];                // bit0 = shift, bit1 = write
__device__ int   g_fin[BB];

__device__ __forceinline__ float sigf(float x) { return 1.0f / (1.0f + expf(-x)); }

// ------------------------- phase A: word GEMM -------------------------------
// C[16384][1024] = A[16384][512] @ W[512][1024] + bias
__global__ __launch_bounds__(256) void word_gemm(
    const float* __restrict__ A, const float* __restrict__ W,
    const float* __restrict__ bias)
{
    __shared__ float As[64][33];
    __shared__ float Bs[32][64];
    const int tx = threadIdx.x & 15;        // 0..15 -> 4 cols each
    const int ty = threadIdx.x >> 4;        // 0..15 -> 4 rows each
    const int rowBase = blockIdx.y * 64;
    const int colBase = blockIdx.x * 64;

    float acc[4][4];
#pragma unroll
    for (int i = 0; i < 4; i++)
#pragma unroll
        for (int j = 0; j < 4; j++) acc[i][j] = 0.f;

    for (int k0 = 0; k0 < EE; k0 += 32) {
#pragma unroll
        for (int i = 0; i < 8; i++) {
            int idx = threadIdx.x + i * 256;
            int r = idx >> 5, c = idx & 31;
            As[r][c] = A[(rowBase + r) * EE + k0 + c];
        }
#pragma unroll
        for (int i = 0; i < 8; i++) {
            int idx = threadIdx.x + i * 256;
            int r = idx >> 6, c = idx & 63;
            Bs[r][c] = W[(k0 + r) * TWO_H + colBase + c];
        }
        __syncthreads();
#pragma unroll
        for (int kk = 0; kk < 32; kk++) {
            float a0 = As[ty * 4 + 0][kk];
            float a1 = As[ty * 4 + 1][kk];
            float a2 = As[ty * 4 + 2][kk];
            float a3 = As[ty * 4 + 3][kk];
            float4 b4 = *reinterpret_cast<const float4*>(&Bs[kk][tx * 4]);
            acc[0][0] += a0 * b4.x; acc[0][1] += a0 * b4.y; acc[0][2] += a0 * b4.z; acc[0][3] += a0 * b4.w;
            acc[1][0] += a1 * b4.x; acc[1][1] += a1 * b4.y; acc[1][2] += a1 * b4.z; acc[1][3] += a1 * b4.w;
            acc[2][0] += a2 * b4.x; acc[2][1] += a2 * b4.y; acc[2][2] += a2 * b4.z; acc[2][3] += a2 * b4.w;
            acc[3][0] += a3 * b4.x; acc[3][1] += a3 * b4.y; acc[3][2] += a3 * b4.z; acc[3][3] += a3 * b4.w;
        }
        __syncthreads();
    }
#pragma unroll
    for (int i = 0; i < 4; i++)
#pragma unroll
        for (int j = 0; j < 4; j++) {
            int col = colBase + tx * 4 + j;
            g_tmp[(rowBase + ty * 4 + i) * TWO_H + col] = acc[i][j] + bias[col];
        }
}

// ------------------------- phase A: BatchNorm stats -------------------------
__global__ void zero_stats()
{
    int ch = blockIdx.x * blockDim.x + threadIdx.x;
    if (ch < TWO_H) { g_sum[ch] = 0.f; g_sumsq[ch] = 0.f; }
}

// grid (4 ch-groups of 256, 256 row-chunks of 64), block 256
__global__ __launch_bounds__(256) void bn_stats()
{
    int ch = blockIdx.x * 256 + threadIdx.x;
    int rowBase = blockIdx.y * 64;
    float s = 0.f, q = 0.f;
#pragma unroll 4
    for (int r = 0; r < 64; r++) {
        float v = g_tmp[(rowBase + r) * TWO_H + ch];
        s += v; q += v * v;
    }
    atomicAdd(&g_sum[ch], s);
    atomicAdd(&g_sumsq[ch], q);
}

__global__ void bn_finalize(const float* __restrict__ gamma, const float* __restrict__ beta)
{
    int ch = blockIdx.x * blockDim.x + threadIdx.x;
    if (ch >= TWO_H) return;
    const float invN = 1.0f / (float)NLE;
    float mean = g_sum[ch] * invN;
    float var  = g_sumsq[ch] * invN - mean * mean;
    float sc   = gamma[ch] * rsqrtf(var + 1e-5f);
    g_scale[ch] = sc;
    g_shift[ch] = beta[ch] - mean * sc;
}

__global__ __launch_bounds__(256) void bn_apply()
{
    int idx = blockIdx.x * 256 + threadIdx.x;   // < 16384*1024
    int row = idx >> 10;
    int ch  = idx & 1023;
    float v = g_tmp[idx] * g_scale[ch] + g_shift[ch];
    if (ch < HH) g_hbuf[row * HH + ch] = v;
    else         g_cbuf[row * HH + (ch - HH)] = v;
}

// ------------------------- metadata precompute ------------------------------
__global__ void meta_kernel(const int* __restrict__ trans)
{
    int b = threadIdx.x;
    if (b >= BB) return;
    int ptr = 0, bp = 0;
    for (int t = 0; t < TT; t++) {
        int act = trans[b * TT + t];
        int i1 = min(max(ptr - 1, 0), SS - 1);
        int i2 = min(max(ptr - 2, 0), SS - 1);
        int bi = min(max(bp, 0), LL - 1);
        bool is_s = (act == 2);
        bool is_r = (act == 3);
        int pos = is_s ? min(max(ptr, 0), SS - 1) : i2;
        int flg = (is_s ? 1 : 0) | ((is_s || is_r) ? 2 : 0);
        if (!(is_s || is_r)) pos = -1;   // PAD: never matches, never written
        int o = t * BB + b;
        g_i1[o] = i1; g_i2[o] = i2; g_pos[o] = pos; g_bi[o] = bi; g_flg[o] = flg;
        ptr += is_s ? 1 : (is_r ? -1 : 0);
        bp  += is_s ? 1 : 0;
    }
    g_fin[b] = min(max(ptr - 1, 0), SS - 1);
}

// ------------------------- per-step fused kernel ----------------------------
// grid: x = 32 j-tiles (16 cols), y = 4 b-tiles (32 rows); 256 threads.
// Computes a = x @ reduce_W + b for 5 gates, TreeLSTM, shift/reduce select,
// stack scatter, and next-step x gather (race-free: thread owns column (b,j)).
__global__ __launch_bounds__(256) void step_kernel(
    int t, const float* __restrict__ W, const float* __restrict__ br)
{
    __shared__ float Xs[32][36];   // [b_local][k]   (pad -> 16B-aligned rows)
    __shared__ float Ws[80][36];   // [gate*16+j][k] transposed for float4 k-reads

    const int tid = threadIdx.x;
    const int jl = tid & 15;       // 0..15 hidden col within tile
    const int bl = tid >> 4;       // 0..15 -> handles b_local {bl, bl+16}
    const int jt = blockIdx.x;
    const int bt = blockIdx.y;
    const float* __restrict__ xin = g_x[t & 1];
    float* __restrict__ xout = g_x[(t + 1) & 1];

    float acc[2][5];
#pragma unroll
    for (int s = 0; s < 2; s++)
#pragma unroll
        for (int g = 0; g < 5; g++) acc[s][g] = 0.f;

    for (int k0 = 0; k0 < TWO_H; k0 += 32) {
#pragma unroll
        for (int i = 0; i < 4; i++) {
            int idx = tid + i * 256;
            int r = idx >> 5, c = idx & 31;
            Xs[r][c] = xin[(bt * 32 + r) * TWO_H + k0 + c];
        }
#pragma unroll
        for (int i = 0; i < 10; i++) {
            int idx = tid + i * 256;
            int kk = idx / 80, c = idx - kk * 80;
            int g = c >> 4, j = c & 15;
            Ws[c][kk] = W[(k0 + kk) * FIVE_H + g * HH + jt * 16 + j];
        }
        __syncthreads();
#pragma unroll
        for (int kk = 0; kk < 32; kk += 4) {
            float4 x0 = *reinterpret_cast<const float4*>(&Xs[bl][kk]);
            float4 x1 = *reinterpret_cast<const float4*>(&Xs[bl + 16][kk]);
#pragma unroll
            for (int g = 0; g < 5; g++) {
                float4 w = *reinterpret_cast<const float4*>(&Ws[g * 16 + jl][kk]);
                acc[0][g] += x0.x * w.x + x0.y * w.y + x0.z * w.z + x0.w * w.w;
                acc[1][g] += x1.x * w.x + x1.y * w.y + x1.z * w.z + x1.w * w.w;
            }
        }
        __syncthreads();
    }

    const int j = jt * 16 + jl;
    float bias[5];
#pragma unroll
    for (int g = 0; g < 5; g++) bias[g] = br[g * HH + j];

#pragma unroll
    for (int s = 0; s < 2; s++) {
        int b = bt * 32 + bl + s * 16;
        int mo = t * BB + b;
        int i1 = g_i1[mo], i2 = g_i2[mo], pos = g_pos[mo];
        int bi = g_bi[mo],  flg = g_flg[mo];

        float ai  = acc[s][0] + bias[0];
        float afl = acc[s][1] + bias[1];
        float afr = acc[s][2] + bias[2];
        float ao  = acc[s][3] + bias[3];
        float ag  = acc[s][4] + bias[4];

        float cl = g_stack_c[(b * SS + i2) * HH + j];
        float cr = g_stack_c[(b * SS + i1) * HH + j];
        float cred = sigf(afl) * cl + sigf(afr) * cr + sigf(ai) * tanhf(ag);
        float hred = sigf(ao) * tanhf(cred);

        float h, c;
        if (flg & 1) {          // SHIFT: take word buffer
            h = g_hbuf[(b * LL + bi) * HH + j];
            c = g_cbuf[(b * LL + bi) * HH + j];
        } else {
            h = hred; c = cred;
        }
        if (flg & 2) {
            g_stack_h[(b * SS + pos) * HH + j] = h;
            g_stack_c[(b * SS + pos) * HH + j] = c;
        }
        if (t + 1 < TT) {       // produce next step's gather (same-thread ordering)
            int mo2 = (t + 1) * BB + b;
            int i1n = g_i1[mo2], i2n = g_i2[mo2];
            float xl = (i2n == pos) ? h : g_stack_h[(b * SS + i2n) * HH + j];
            float xr = (i1n == pos) ? h : g_stack_h[(b * SS + i1n) * HH + j];
            xout[b * TWO_H + j] = xl;
            xout[b * TWO_H + HH + j] = xr;
        }
    }
}

// ------------------------- final readout ------------------------------------
__global__ void final_kernel(float* __restrict__ out)
{
    int idx = blockIdx.x * blockDim.x + threadIdx.x;   // < 128*512
    if (idx >= BB * HH) return;
    int b = idx >> 9;
    int j = idx & 511;
    out[idx] = g_stack_h[(b * SS + g_fin[b]) * HH + j];
}

// ------------------------- launch -------------------------------------------
extern "C" void kernel_launch(void* const* d_in, const int* in_sizes, int n_in,
                              void* d_out, int out_size)
{
    const float* sentence    = (const float*)d_in[0];
    const int*   transitions = (const int*)  d_in[1];
    const float* word_W      = (const float*)d_in[2];
    const float* word_b      = (const float*)d_in[3];
    const float* bn_gamma    = (const float*)d_in[4];
    const float* bn_beta     = (const float*)d_in[5];
    const float* reduce_W    = (const float*)d_in[6];
    const float* reduce_b    = (const float*)d_in[7];
    float* out = (float*)d_out;

    // Phase A: word projection + batchnorm
    word_gemm<<<dim3(TWO_H / 64, NLE / 64), 256>>>(sentence, word_W, word_b);
    zero_stats<<<4, 256>>>();
    bn_stats<<<dim3(4, 256), 256>>>();
    bn_finalize<<<4, 256>>>(bn_gamma, bn_beta);
    bn_apply<<<(NLE * TWO_H) / 256, 256>>>();

    // Pointer metadata (data-independent)
    meta_kernel<<<1, 128>>>(transitions);

    // Sequential scan
    for (int t = 0; t < TT; t++) {
        step_kernel<<<dim3(32, 4), 256>>>(t, reduce_W, reduce_b);
    }

    final_kernel<<<(BB * HH + 255) / 256, 256>>>(out);
}